// round 3
// baseline (speedup 1.0000x reference)
#include <cuda_runtime.h>

// Problem constants
#define BB 128
#define TT 100
#define II 1024
#define OO 1024
#define MROWS (BB * TT)   // 12800

// Scratch (static device globals; allocation is forbidden)
__device__ float g_h[(size_t)MROWS * OO];     // x @ w   [12800,1024]  ~52MB
__device__ float g_d[(size_t)II * OO];        // w^T w   [1024,1024]   4MB
__device__ float g_inv_norm[OO];              // 1/(sum w^2 + eps)
__device__ int   g_tcount[TT];                // spikes per timestep

// ---------------------------------------------------------------------------
// init: zero per-timestep counters
// ---------------------------------------------------------------------------
__global__ void init_kernel() {
    int t = threadIdx.x;
    if (t < TT) g_tcount[t] = 0;
}

// ---------------------------------------------------------------------------
// SGEMM NN: C[M,N] = A[M,K] * B[K,N]  (M%128==0, N%128==0, K%8==0)
// 128x128 block tile, BK=8, 256 threads, 8x8 register tile per thread.
// ---------------------------------------------------------------------------
__global__ __launch_bounds__(256) void sgemm_nn(
    const float* __restrict__ A, const float* __restrict__ B,
    float* __restrict__ C, int M, int N, int K)
{
    __shared__ float As[8][128];
    __shared__ float Bs[8][128];

    int tid = threadIdx.x;
    int tx = tid & 15;        // 0..15 -> col group
    int ty = tid >> 4;        // 0..15 -> row group
    int rowBase = blockIdx.y * 128;
    int colBase = blockIdx.x * 128;

    // A loader: 128 rows x 8 k; one float4 per thread along K
    int arow = tid >> 1;            // 0..127
    int ak4  = (tid & 1) * 4;       // 0 or 4
    // B loader: 8 rows x 128 cols; one float4 per thread along N
    int brow  = tid >> 5;           // 0..7
    int bcol4 = (tid & 31) * 4;     // 0..124

    const float* Aptr = A + (size_t)(rowBase + arow) * K + ak4;
    const float* Bptr = B + (size_t)brow * N + colBase + bcol4;

    float acc[8][8];
    #pragma unroll
    for (int i = 0; i < 8; i++)
        #pragma unroll
        for (int j = 0; j < 8; j++) acc[i][j] = 0.f;

    for (int k0 = 0; k0 < K; k0 += 8) {
        float4 av = *(const float4*)(Aptr + k0);
        float4 bv = *(const float4*)(Bptr + (size_t)k0 * N);
        __syncthreads();   // previous iteration's shared reads done
        As[ak4 + 0][arow] = av.x;
        As[ak4 + 1][arow] = av.y;
        As[ak4 + 2][arow] = av.z;
        As[ak4 + 3][arow] = av.w;
        *(float4*)&Bs[brow][bcol4] = bv;
        __syncthreads();
        #pragma unroll
        for (int k = 0; k < 8; k++) {
            float4 a0 = *(const float4*)&As[k][ty * 4];
            float4 a1 = *(const float4*)&As[k][ty * 4 + 64];
            float4 b0 = *(const float4*)&Bs[k][tx * 4];
            float4 b1 = *(const float4*)&Bs[k][tx * 4 + 64];
            float ar[8] = {a0.x, a0.y, a0.z, a0.w, a1.x, a1.y, a1.z, a1.w};
            float br[8] = {b0.x, b0.y, b0.z, b0.w, b1.x, b1.y, b1.z, b1.w};
            #pragma unroll
            for (int i = 0; i < 8; i++)
                #pragma unroll
                for (int j = 0; j < 8; j++)
                    acc[i][j] = fmaf(ar[i], br[j], acc[i][j]);
        }
    }

    #pragma unroll
    for (int i = 0; i < 8; i++) {
        int r = rowBase + ((i < 4) ? (ty * 4 + i) : (ty * 4 + 64 + i - 4));
        float4 c0 = make_float4(acc[i][0], acc[i][1], acc[i][2], acc[i][3]);
        float4 c1 = make_float4(acc[i][4], acc[i][5], acc[i][6], acc[i][7]);
        *(float4*)&C[(size_t)r * N + colBase + tx * 4]      = c0;
        *(float4*)&C[(size_t)r * N + colBase + tx * 4 + 64] = c1;
    }
}

// ---------------------------------------------------------------------------
// d = w^T w : C[i][o] = sum_a W[a][i]*W[a][o], all dims 1024.
// Both tiles load coalesced rows of W directly (no transpose in smem).
// ---------------------------------------------------------------------------
__global__ __launch_bounds__(256) void sgemm_tn_ww(
    const float* __restrict__ W, float* __restrict__ C)
{
    __shared__ float As[8][128];
    __shared__ float Bs[8][128];

    int tid = threadIdx.x;
    int tx = tid & 15;
    int ty = tid >> 4;
    int iBase = blockIdx.y * 128;
    int oBase = blockIdx.x * 128;

    int lrow  = tid >> 5;         // 0..7
    int lcol4 = (tid & 31) * 4;   // 0..124

    float acc[8][8];
    #pragma unroll
    for (int i = 0; i < 8; i++)
        #pragma unroll
        for (int j = 0; j < 8; j++) acc[i][j] = 0.f;

    for (int k0 = 0; k0 < II; k0 += 8) {
        float4 av = *(const float4*)&W[(size_t)(k0 + lrow) * OO + iBase + lcol4];
        float4 bv = *(const float4*)&W[(size_t)(k0 + lrow) * OO + oBase + lcol4];
        __syncthreads();
        *(float4*)&As[lrow][lcol4] = av;
        *(float4*)&Bs[lrow][lcol4] = bv;
        __syncthreads();
        #pragma unroll
        for (int k = 0; k < 8; k++) {
            float4 a0 = *(const float4*)&As[k][ty * 4];
            float4 a1 = *(const float4*)&As[k][ty * 4 + 64];
            float4 b0 = *(const float4*)&Bs[k][tx * 4];
            float4 b1 = *(const float4*)&Bs[k][tx * 4 + 64];
            float ar[8] = {a0.x, a0.y, a0.z, a0.w, a1.x, a1.y, a1.z, a1.w};
            float br[8] = {b0.x, b0.y, b0.z, b0.w, b1.x, b1.y, b1.z, b1.w};
            #pragma unroll
            for (int i = 0; i < 8; i++)
                #pragma unroll
                for (int j = 0; j < 8; j++)
                    acc[i][j] = fmaf(ar[i], br[j], acc[i][j]);
        }
    }

    #pragma unroll
    for (int i = 0; i < 8; i++) {
        int r = iBase + ((i < 4) ? (ty * 4 + i) : (ty * 4 + 64 + i - 4));
        float4 c0 = make_float4(acc[i][0], acc[i][1], acc[i][2], acc[i][3]);
        float4 c1 = make_float4(acc[i][4], acc[i][5], acc[i][6], acc[i][7]);
        *(float4*)&C[(size_t)r * OO + oBase + tx * 4]      = c0;
        *(float4*)&C[(size_t)r * OO + oBase + tx * 4 + 64] = c1;
    }
}

// ---------------------------------------------------------------------------
// inv_norm[o] = 1 / (sum_a W[a][o]^2 + 1e-8)
// ---------------------------------------------------------------------------
__global__ void norm_kernel(const float* __restrict__ W) {
    int o = blockIdx.x * blockDim.x + threadIdx.x;
    if (o >= OO) return;
    float s = 0.f;
    for (int a = 0; a < II; a++) {
        float x = W[(size_t)a * OO + o];
        s = fmaf(x, x, s);
    }
    g_inv_norm[o] = 1.0f / (s + 1e-8f);
}

// ---------------------------------------------------------------------------
// Fused scan: one block per batch row, 1024 threads (one per neuron).
// mem state in registers; spikes compacted into a shared index list
// (spk is binary & extremely sparse -> lateral/recurrent terms become
// a tiny gather over d/v rows, served from L2).
// ---------------------------------------------------------------------------
__global__ __launch_bounds__(1024) void scan_kernel(
    const float* __restrict__ hmat,   // g_h
    const float* __restrict__ dmat,   // g_d
    const float* __restrict__ v,
    const float* __restrict__ beta_p,
    const float* __restrict__ b_p,
    float* __restrict__ out)
{
    int b = blockIdx.x;
    int o = threadIdx.x;

    __shared__ int s_list[2][OO];
    __shared__ int s_cnt[2];

    float beta = beta_p[0];
    float ombeta = 1.0f - beta;
    float inv_n = g_inv_norm[o];
    float bo = b_p[o];
    float mem = 0.f;

    if (o == 0) { s_cnt[0] = 0; s_cnt[1] = 0; }
    __syncthreads();

    const float* hrow = hmat + (size_t)b * TT * OO;
    // 2-deep prefetch of h_t to hide DRAM latency
    float hbuf0 = hrow[(size_t)0 * OO + o];
    float hbuf1 = hrow[(size_t)1 * OO + o];

    for (int t = 0; t < TT; t++) {
        int cur = t & 1;
        int nxt = cur ^ 1;
        float hcur = (t & 1) ? hbuf1 : hbuf0;
        float hpre = 0.f;
        if (t + 2 < TT) hpre = hrow[(size_t)(t + 2) * OO + o];

        int cnt = s_cnt[cur];
        if (o == 0) s_cnt[nxt] = 0;
        __syncthreads();

        float rst = 0.f, rec = 0.f;
        for (int s = 0; s < cnt; s++) {
            int idx = s_list[cur][s];
            rst += dmat[(size_t)idx * OO + o];
            rec += v[(size_t)idx * OO + o];
        }

        mem = (mem - rst) * beta + (hcur + rec) * ombeta;
        float mthr = mem * inv_n - bo;
        float spk = (mthr > 0.f) ? 1.0f : 0.0f;
        out[((size_t)b * TT + t) * OO + o] = spk;

        if (mthr > 0.f) {
            int p = atomicAdd(&s_cnt[nxt], 1);
            s_list[nxt][p] = o;
        }
        __syncthreads();

        if (o == 0) {
            int c = s_cnt[nxt];
            if (c) atomicAdd(&g_tcount[t], c);
        }

        if (t & 1) hbuf1 = hpre; else hbuf0 = hpre;
    }
}

// ---------------------------------------------------------------------------
// Finalize: loss = 0.5 * total/(B*T*O) ; spread = max_t count[t] / (B*O)
// ---------------------------------------------------------------------------
__global__ void finalize_kernel(float* __restrict__ out, int out_size) {
    if (threadIdx.x == 0) {
        long long total = 0;
        int mx = 0;
        for (int t = 0; t < TT; t++) {
            int c = g_tcount[t];
            total += c;
            if (c > mx) mx = c;
        }
        size_t base = (size_t)MROWS * OO;
        if ((size_t)out_size >= base + 2) {
            out[base]     = 0.5f * ((float)total / (float)((size_t)MROWS * OO));
            out[base + 1] = (float)mx / (float)(BB * OO);
        }
    }
}

// ---------------------------------------------------------------------------
extern "C" void kernel_launch(void* const* d_in, const int* in_sizes, int n_in,
                              void* d_out, int out_size)
{
    const float* x    = (const float*)d_in[0];  // [B,T,I]
    const float* w    = (const float*)d_in[1];  // [I,O]
    const float* v    = (const float*)d_in[2];  // [O,O]
    const float* beta = (const float*)d_in[3];  // [1]
    const float* b    = (const float*)d_in[4];  // [O]
    // d_in[5] = sigma (unused in forward)
    float* out = (float*)d_out;

    float* h_ptr = nullptr;
    float* d_ptr = nullptr;
    cudaGetSymbolAddress((void**)&h_ptr, g_h);
    cudaGetSymbolAddress((void**)&d_ptr, g_d);

    init_kernel<<<1, 128>>>();

    // d = w^T w   (1024x1024, grid 8x8)
    sgemm_tn_ww<<<dim3(8, 8), 256>>>(w, d_ptr);

    // inv_norm
    norm_kernel<<<4, 256>>>(w);

    // h = x @ w   (12800x1024x1024, grid 8x100)
    sgemm_nn<<<dim3(8, 100), 256>>>(x, w, h_ptr, MROWS, OO, II);

    // fused temporal scan (one block per batch row)
    scan_kernel<<<BB, 1024>>>(h_ptr, d_ptr, v, beta, b, out);

    // scalar outputs
    finalize_kernel<<<1, 32>>>(out, out_size);
}

// round 7
// speedup vs baseline: 1.7722x; 1.7722x over previous
#include <cuda_runtime.h>
#include <cuda_bf16.h>
#include <cstdint>

// Problem constants
#define BB 128
#define TT 100
#define II 1024
#define OO 1024
#define MROWS (BB * TT)   // 12800

// ---------------------------------------------------------------------------
// Scratch (static device globals; allocation is forbidden)
// ---------------------------------------------------------------------------
__device__ float g_h[(size_t)MROWS * OO];              // x @ w  [12800,1024]
__device__ float g_d[(size_t)II * OO];                 // w^T w  [1024,1024]
__device__ float g_inv_norm[OO];
__device__ int   g_tcount[TT];
__device__ __nv_bfloat16 g_xhi[(size_t)MROWS * II];    // bf16 split of x (hi)
__device__ __nv_bfloat16 g_xlo[(size_t)MROWS * II];    // bf16 split of x (lo)
__device__ __nv_bfloat16 g_whi[(size_t)OO * II];       // w^T split hi: [n][k]=w[k][n]
__device__ __nv_bfloat16 g_wlo[(size_t)OO * II];       // w^T split lo

// ---------------------------------------------------------------------------
// init: zero per-timestep counters
// ---------------------------------------------------------------------------
__global__ void init_kernel() {
    int t = threadIdx.x;
    if (t < TT) g_tcount[t] = 0;
}

// ---------------------------------------------------------------------------
// Split x into bf16 hi/lo (row-major layout preserved)
// ---------------------------------------------------------------------------
__global__ __launch_bounds__(256) void split_x_kernel(const float* __restrict__ x) {
    size_t i4 = ((size_t)blockIdx.x * blockDim.x + threadIdx.x) * 4;
    if (i4 + 3 >= (size_t)MROWS * II) return;
    float4 v = *(const float4*)&x[i4];
    float f[4] = {v.x, v.y, v.z, v.w};
    __nv_bfloat16 hi[4], lo[4];
#pragma unroll
    for (int j = 0; j < 4; j++) {
        hi[j] = __float2bfloat16(f[j]);
        lo[j] = __float2bfloat16(f[j] - __bfloat162float(hi[j]));
    }
    __nv_bfloat162 h0; h0.x = hi[0]; h0.y = hi[1];
    __nv_bfloat162 h1; h1.x = hi[2]; h1.y = hi[3];
    __nv_bfloat162 l0; l0.x = lo[0]; l0.y = lo[1];
    __nv_bfloat162 l1; l1.x = lo[2]; l1.y = lo[3];
    *(__nv_bfloat162*)&g_xhi[i4]     = h0;
    *(__nv_bfloat162*)&g_xhi[i4 + 2] = h1;
    *(__nv_bfloat162*)&g_xlo[i4]     = l0;
    *(__nv_bfloat162*)&g_xlo[i4 + 2] = l1;
}

// ---------------------------------------------------------------------------
// Transpose + split w: g_whi[n][k] = bf16(w[k][n]), g_wlo = residual
// ---------------------------------------------------------------------------
__global__ __launch_bounds__(256) void split_w_kernel(const float* __restrict__ w) {
    __shared__ float t[32][33];
    int n0 = blockIdx.x * 32;
    int k0 = blockIdx.y * 32;
#pragma unroll
    for (int j = 0; j < 32; j += 8)
        t[threadIdx.y + j][threadIdx.x] = w[(size_t)(k0 + threadIdx.y + j) * OO + n0 + threadIdx.x];
    __syncthreads();
#pragma unroll
    for (int j = 0; j < 32; j += 8) {
        float v = t[threadIdx.x][threadIdx.y + j];          // = w[k0+tx][n0+ty+j]
        __nv_bfloat16 hi = __float2bfloat16(v);
        __nv_bfloat16 lo = __float2bfloat16(v - __bfloat162float(hi));
        size_t o = (size_t)(n0 + threadIdx.y + j) * II + k0 + threadIdx.x;
        g_whi[o] = hi;
        g_wlo[o] = lo;
    }
}

// ---------------------------------------------------------------------------
// inv_norm from the diagonal of d = w^T w  (d[o][o] = sum_a w[a][o]^2)
// ---------------------------------------------------------------------------
__global__ void invnorm_kernel() {
    int o = blockIdx.x * blockDim.x + threadIdx.x;
    if (o < OO) g_inv_norm[o] = 1.0f / (g_d[(size_t)o * OO + o] + 1e-8f);
}

// ---------------------------------------------------------------------------
// HMMA bf16x3 GEMM: C[m][n] = sum_k A[m][k] * B[n][k]  (fp32 accumulate)
// A = Ahi+Alo, B = Bhi+Blo bf16 splits; computes AhiBhi + AhiBlo + AloBhi.
// mma.sync.aligned.m16n8k16.row.col.f32.bf16.bf16.f32 (compute_80 PTX —
// assembles for the plain sm_103 target this toolchain emits; tcgen05 does not).
// 128x128 CTA tile, BK=32, 256 threads = 8 warps (4m x 2n), warp tile 32x64.
// Register-staged global prefetch overlaps LDG with MMA.
// ---------------------------------------------------------------------------
#define BKC 32
#define AST 40   // smem row stride in bf16 (32 data + 8 pad) -> 80B, conflict-free

__device__ __forceinline__ void mma16816(float* d, const uint32_t* a, const uint32_t* b) {
    asm volatile(
        "mma.sync.aligned.m16n8k16.row.col.f32.bf16.bf16.f32 "
        "{%0,%1,%2,%3}, {%4,%5,%6,%7}, {%8,%9}, {%0,%1,%2,%3};"
        : "+f"(d[0]), "+f"(d[1]), "+f"(d[2]), "+f"(d[3])
        : "r"(a[0]), "r"(a[1]), "r"(a[2]), "r"(a[3]), "r"(b[0]), "r"(b[1]));
}

__global__ __launch_bounds__(256, 1) void hmma_gemm_bf16x3(
    const __nv_bfloat16* __restrict__ Ahi, const __nv_bfloat16* __restrict__ Alo,
    const __nv_bfloat16* __restrict__ Bhi, const __nv_bfloat16* __restrict__ Blo,
    float* __restrict__ C)
{
    __shared__ __nv_bfloat16 sAh[128][AST];
    __shared__ __nv_bfloat16 sAl[128][AST];
    __shared__ __nv_bfloat16 sBh[128][AST];
    __shared__ __nv_bfloat16 sBl[128][AST];

    int tid  = threadIdx.x;
    int lane = tid & 31;
    int wid  = tid >> 5;
    int warpM = (wid >> 1) * 32;   // 0,32,64,96
    int warpN = (wid & 1) * 64;    // 0,64
    int rowBase = blockIdx.y * 128;
    int colBase = blockIdx.x * 128;

    int gi = lane >> 2;            // group id 0..7
    int tg = lane & 3;             // thread in group

    // global loader: thread covers row (tid>>1), 16 cols starting at (tid&1)*16
    int ldrow = tid >> 1;
    int ldc0  = (tid & 1) * 16;

    const __nv_bfloat16* gA0 = Ahi + (size_t)(rowBase + ldrow) * II + ldc0;
    const __nv_bfloat16* gA1 = Alo + (size_t)(rowBase + ldrow) * II + ldc0;
    const __nv_bfloat16* gB0 = Bhi + (size_t)(colBase + ldrow) * II + ldc0;
    const __nv_bfloat16* gB1 = Blo + (size_t)(colBase + ldrow) * II + ldc0;

    float acc[2][8][4];
#pragma unroll
    for (int i = 0; i < 2; i++)
#pragma unroll
        for (int j = 0; j < 8; j++)
#pragma unroll
            for (int q = 0; q < 4; q++) acc[i][j][q] = 0.f;

    uint4 rAh0, rAh1, rAl0, rAl1, rBh0, rBh1, rBl0, rBl1;
    // preload chunk 0
    {
        rAh0 = *(const uint4*)(gA0);      rAh1 = *(const uint4*)(gA0 + 8);
        rAl0 = *(const uint4*)(gA1);      rAl1 = *(const uint4*)(gA1 + 8);
        rBh0 = *(const uint4*)(gB0);      rBh1 = *(const uint4*)(gB0 + 8);
        rBl0 = *(const uint4*)(gB1);      rBl1 = *(const uint4*)(gB1 + 8);
    }

    const int NCH = II / BKC;   // 32
    for (int c = 0; c < NCH; c++) {
        __syncthreads();   // previous compute done before overwriting smem
        *(uint4*)&sAh[ldrow][ldc0]     = rAh0;
        *(uint4*)&sAh[ldrow][ldc0 + 8] = rAh1;
        *(uint4*)&sAl[ldrow][ldc0]     = rAl0;
        *(uint4*)&sAl[ldrow][ldc0 + 8] = rAl1;
        *(uint4*)&sBh[ldrow][ldc0]     = rBh0;
        *(uint4*)&sBh[ldrow][ldc0 + 8] = rBh1;
        *(uint4*)&sBl[ldrow][ldc0]     = rBl0;
        *(uint4*)&sBl[ldrow][ldc0 + 8] = rBl1;
        __syncthreads();

        if (c + 1 < NCH) {
            int k0 = (c + 1) * BKC;
            rAh0 = *(const uint4*)(gA0 + k0);  rAh1 = *(const uint4*)(gA0 + k0 + 8);
            rAl0 = *(const uint4*)(gA1 + k0);  rAl1 = *(const uint4*)(gA1 + k0 + 8);
            rBh0 = *(const uint4*)(gB0 + k0);  rBh1 = *(const uint4*)(gB0 + k0 + 8);
            rBl0 = *(const uint4*)(gB1 + k0);  rBl1 = *(const uint4*)(gB1 + k0 + 8);
        }

#pragma unroll
        for (int kk = 0; kk < BKC; kk += 16) {
            uint32_t ah[2][4], al[2][4], bh[8][2], bl[8][2];
            int kc = kk + tg * 2;
#pragma unroll
            for (int mi = 0; mi < 2; mi++) {
                int r = warpM + mi * 16 + gi;
                ah[mi][0] = *(const uint32_t*)&sAh[r][kc];
                ah[mi][1] = *(const uint32_t*)&sAh[r + 8][kc];
                ah[mi][2] = *(const uint32_t*)&sAh[r][kc + 8];
                ah[mi][3] = *(const uint32_t*)&sAh[r + 8][kc + 8];
                al[mi][0] = *(const uint32_t*)&sAl[r][kc];
                al[mi][1] = *(const uint32_t*)&sAl[r + 8][kc];
                al[mi][2] = *(const uint32_t*)&sAl[r][kc + 8];
                al[mi][3] = *(const uint32_t*)&sAl[r + 8][kc + 8];
            }
#pragma unroll
            for (int nj = 0; nj < 8; nj++) {
                int n = warpN + nj * 8 + gi;
                bh[nj][0] = *(const uint32_t*)&sBh[n][kc];
                bh[nj][1] = *(const uint32_t*)&sBh[n][kc + 8];
                bl[nj][0] = *(const uint32_t*)&sBl[n][kc];
                bl[nj][1] = *(const uint32_t*)&sBl[n][kc + 8];
            }
#pragma unroll
            for (int mi = 0; mi < 2; mi++)
#pragma unroll
                for (int nj = 0; nj < 8; nj++) {
                    mma16816(acc[mi][nj], ah[mi], bh[nj]);   // hi*hi
                    mma16816(acc[mi][nj], ah[mi], bl[nj]);   // hi*lo
                    mma16816(acc[mi][nj], al[mi], bh[nj]);   // lo*hi
                }
        }
    }

    // Epilogue
#pragma unroll
    for (int mi = 0; mi < 2; mi++) {
        int r0 = rowBase + warpM + mi * 16 + gi;
#pragma unroll
        for (int nj = 0; nj < 8; nj++) {
            int c0 = colBase + warpN + nj * 8 + tg * 2;
            float2 v0 = make_float2(acc[mi][nj][0], acc[mi][nj][1]);
            float2 v1 = make_float2(acc[mi][nj][2], acc[mi][nj][3]);
            *(float2*)&C[(size_t)r0 * OO + c0]       = v0;
            *(float2*)&C[(size_t)(r0 + 8) * OO + c0] = v1;
        }
    }
}

// ---------------------------------------------------------------------------
// Fused temporal scan: one block per batch row, 1024 threads (1 per neuron).
// Spikes compacted into shared index list (binary & extremely sparse).
// ---------------------------------------------------------------------------
__global__ __launch_bounds__(1024) void scan_kernel(
    const float* __restrict__ hmat,
    const float* __restrict__ dmat,
    const float* __restrict__ v,
    const float* __restrict__ beta_p,
    const float* __restrict__ b_p,
    float* __restrict__ out)
{
    int b = blockIdx.x;
    int o = threadIdx.x;

    __shared__ int s_list[2][OO];
    __shared__ int s_cnt[2];

    float beta = beta_p[0];
    float ombeta = 1.0f - beta;
    float inv_n = g_inv_norm[o];
    float bo = b_p[o];
    float mem = 0.f;

    if (o == 0) { s_cnt[0] = 0; s_cnt[1] = 0; }
    __syncthreads();

    const float* hrow = hmat + (size_t)b * TT * OO;
    float hbuf0 = hrow[(size_t)0 * OO + o];
    float hbuf1 = hrow[(size_t)1 * OO + o];

    for (int t = 0; t < TT; t++) {
        int cur = t & 1;
        int nxt = cur ^ 1;
        float hcur = (t & 1) ? hbuf1 : hbuf0;
        float hpre = 0.f;
        if (t + 2 < TT) hpre = hrow[(size_t)(t + 2) * OO + o];

        int cnt = s_cnt[cur];
        if (o == 0) s_cnt[nxt] = 0;
        __syncthreads();

        float rst = 0.f, rec = 0.f;
        for (int s = 0; s < cnt; s++) {
            int idx = s_list[cur][s];
            rst += dmat[(size_t)idx * OO + o];
            rec += v[(size_t)idx * OO + o];
        }

        mem = (mem - rst) * beta + (hcur + rec) * ombeta;
        float mthr = mem * inv_n - bo;
        float spk = (mthr > 0.f) ? 1.0f : 0.0f;
        out[((size_t)b * TT + t) * OO + o] = spk;

        if (mthr > 0.f) {
            int p = atomicAdd(&s_cnt[nxt], 1);
            s_list[nxt][p] = o;
        }
        __syncthreads();

        if (o == 0) {
            int cc = s_cnt[nxt];
            if (cc) atomicAdd(&g_tcount[t], cc);
        }

        if (t & 1) hbuf1 = hpre; else hbuf0 = hpre;
    }
}

// ---------------------------------------------------------------------------
// Finalize scalars
// ---------------------------------------------------------------------------
__global__ void finalize_kernel(float* __restrict__ out, int out_size) {
    if (threadIdx.x == 0) {
        long long total = 0;
        int mx = 0;
        for (int t = 0; t < TT; t++) {
            int cc = g_tcount[t];
            total += cc;
            if (cc > mx) mx = cc;
        }
        size_t base = (size_t)MROWS * OO;
        if ((size_t)out_size >= base + 2) {
            out[base]     = 0.5f * ((float)total / (float)((size_t)MROWS * OO));
            out[base + 1] = (float)mx / (float)(BB * OO);
        }
    }
}

// ---------------------------------------------------------------------------
extern "C" void kernel_launch(void* const* d_in, const int* in_sizes, int n_in,
                              void* d_out, int out_size)
{
    const float* x    = (const float*)d_in[0];  // [B,T,I]
    const float* w    = (const float*)d_in[1];  // [I,O]
    const float* v    = (const float*)d_in[2];  // [O,O]
    const float* beta = (const float*)d_in[3];  // [1]
    const float* b    = (const float*)d_in[4];  // [O]
    float* out = (float*)d_out;

    float *h_ptr = nullptr, *d_ptr = nullptr;
    __nv_bfloat16 *xhi = nullptr, *xlo = nullptr, *whi = nullptr, *wlo = nullptr;
    cudaGetSymbolAddress((void**)&h_ptr, g_h);
    cudaGetSymbolAddress((void**)&d_ptr, g_d);
    cudaGetSymbolAddress((void**)&xhi, g_xhi);
    cudaGetSymbolAddress((void**)&xlo, g_xlo);
    cudaGetSymbolAddress((void**)&whi, g_whi);
    cudaGetSymbolAddress((void**)&wlo, g_wlo);

    init_kernel<<<1, 128>>>();

    // bf16 splits
    split_x_kernel<<<(MROWS * II / 4 + 255) / 256, 256>>>(x);
    split_w_kernel<<<dim3(32, 32), dim3(32, 8)>>>(w);

    // d = w^T w via tensor cores: d[i][o] = sum_k Wt[i][k] * Wt[o][k]
    hmma_gemm_bf16x3<<<dim3(8, 8), 256>>>(whi, wlo, whi, wlo, d_ptr);

    // inv_norm from diagonal of d
    invnorm_kernel<<<4, 256>>>();

    // h = x @ w via tensor cores: h[m][o] = sum_k X[m][k] * Wt[o][k]
    hmma_gemm_bf16x3<<<dim3(8, 100), 256>>>(xhi, xlo, whi, wlo, h_ptr);

    // fused temporal scan
    scan_kernel<<<BB, 1024>>>(h_ptr, d_ptr, v, beta, b, out);

    finalize_kernel<<<1, 32>>>(out, out_size);
}